// round 3
// baseline (speedup 1.0000x reference)
#include <cuda_runtime.h>
#include <math.h>

#define NN 100000
#define NE 1600000
#define DD 64
#define NG 512
#define NT 100

// ---------------- device scratch (no allocations allowed) ----------------
__device__ __align__(16) float g_h[NN * DD];      // x @ W result
__device__ __align__(16) float g_agg[NN * DD];    // aggregation target
__device__ __align__(16) float g_feat[NN * DD];   // layer output features
__device__ float g_deg[NN];
__device__ float g_dinv[NN];
__device__ float g_norm[NE];
__device__ __align__(16) float g_pooled[NG * DD];
__device__ float g_cnt[NG];

// vectorized global reduction (sm_90+): 4 floats per atomic message
__device__ __forceinline__ void red4(float* p, float4 v) {
    asm volatile("red.global.add.v4.f32 [%0], {%1, %2, %3, %4};"
                 :: "l"(p), "f"(v.x), "f"(v.y), "f"(v.z), "f"(v.w)
                 : "memory");
}

// ---------------- graph-structure prep (once per launch) ----------------
__global__ void k_zero_deg() {
    int i = blockIdx.x * blockDim.x + threadIdx.x;
    if (i < NN) g_deg[i] = 0.f;
}

__global__ void k_deg(const int* __restrict__ dst) {
    int e = blockIdx.x * blockDim.x + threadIdx.x;
    if (e < NE) atomicAdd(&g_deg[dst[e]], 1.f);
}

__global__ void k_dinv() {
    int i = blockIdx.x * blockDim.x + threadIdx.x;
    if (i < NN) g_dinv[i] = rsqrtf(g_deg[i] + 1.f);
}

__global__ void k_norm(const int* __restrict__ src, const int* __restrict__ dst) {
    int e = blockIdx.x * blockDim.x + threadIdx.x;
    if (e < NE) g_norm[e] = g_dinv[src[e]] * g_dinv[dst[e]];
}

// ---------------- GEMM: C[n,64] = A[n,64] @ W[64,64] ----------------
// 256 threads, 16 rows per block; each thread computes 4 outputs.
__global__ void k_gemm(const float* __restrict__ A, const float* __restrict__ W,
                       float* __restrict__ C) {
    __shared__ float sW[DD * DD];
    __shared__ float sA[16 * DD];
    int tid = threadIdx.x;
    long base = (long)blockIdx.x * 16 * DD;
#pragma unroll
    for (int i = 0; i < 16; i++) sW[tid + i * 256] = W[tid + i * 256];
#pragma unroll
    for (int i = 0; i < 4; i++) sA[tid + i * 256] = A[base + tid + i * 256];
    __syncthreads();
    int col = tid & 63;
    int r0 = tid >> 6;  // 0..3
    float a0 = 0.f, a1 = 0.f, a2 = 0.f, a3 = 0.f;
#pragma unroll
    for (int k = 0; k < DD; k++) {
        float w = sW[k * DD + col];
        a0 = fmaf(sA[(r0     ) * DD + k], w, a0);
        a1 = fmaf(sA[(r0 +  4) * DD + k], w, a1);
        a2 = fmaf(sA[(r0 +  8) * DD + k], w, a2);
        a3 = fmaf(sA[(r0 + 12) * DD + k], w, a3);
    }
    C[base + (r0     ) * DD + col] = a0;
    C[base + (r0 +  4) * DD + col] = a1;
    C[base + (r0 +  8) * DD + col] = a2;
    C[base + (r0 + 12) * DD + col] = a3;
}

// ---------------- agg = h * dinv^2 + b  (self-loop + bias, replaces zeroing) ----
__global__ void k_init_agg(const float* __restrict__ b) {
    int t = blockIdx.x * blockDim.x + threadIdx.x;  // NN*16 threads
    if (t >= NN * 16) return;
    int node = t >> 4, g = t & 15;
    float di = g_dinv[node];
    float d2 = di * di;
    float4 h  = *(const float4*)(g_h + (long)node * DD + g * 4);
    float4 bb = *(const float4*)(b + g * 4);
    float4 o;
    o.x = fmaf(h.x, d2, bb.x);
    o.y = fmaf(h.y, d2, bb.y);
    o.z = fmaf(h.z, d2, bb.z);
    o.w = fmaf(h.w, d2, bb.w);
    *(float4*)(g_agg + (long)node * DD + g * 4) = o;
}

// ---------------- edge scatter: agg[dst] += h[src] * norm ----------------
__global__ void k_scatter(const int* __restrict__ src, const int* __restrict__ dst) {
    long t = (long)blockIdx.x * blockDim.x + threadIdx.x;  // NE*16 threads exactly
    int e = (int)(t >> 4), g = (int)(t & 15);
    int s = src[e], d = dst[e];
    float n = g_norm[e];
    float4 h = *(const float4*)(g_h + (long)s * DD + g * 4);
    float4 v;
    v.x = h.x * n; v.y = h.y * n; v.z = h.z * n; v.w = h.w * n;
    red4(g_agg + (long)d * DD + g * 4, v);
}

// ---------------- relu: feat = max(agg, 0) ----------------
__global__ void k_relu() {
    int t = blockIdx.x * blockDim.x + threadIdx.x;  // NN*16 threads
    if (t >= NN * 16) return;
    float4 a = *(const float4*)(g_agg + (long)t * 4);
    a.x = fmaxf(a.x, 0.f); a.y = fmaxf(a.y, 0.f);
    a.z = fmaxf(a.z, 0.f); a.w = fmaxf(a.w, 0.f);
    *(float4*)(g_feat + (long)t * 4) = a;
}

// ---------------- pooling ----------------
__global__ void k_zero_pool() {
    int i = blockIdx.x * blockDim.x + threadIdx.x;
    if (i < NG * DD) g_pooled[i] = 0.f;
    if (i < NG) g_cnt[i] = 0.f;
}

__global__ void k_count(const int* __restrict__ bs) {
    int i = blockIdx.x * blockDim.x + threadIdx.x;
    if (i < NN) atomicAdd(&g_cnt[bs[i]], 1.f);
}

__global__ void k_pool(const int* __restrict__ bs) {
    int t = blockIdx.x * blockDim.x + threadIdx.x;  // NN*16 threads
    if (t >= NN * 16) return;
    int node = t >> 4, g = t & 15;
    int gr = bs[node];
    float4 v = *(const float4*)(g_agg + (long)node * DD + g * 4);  // layer 3: no relu
    red4(g_pooled + (long)gr * DD + g * 4, v);
}

// ---------------- output projection: out = (pooled/cnt) @ Wout + bout ----
__global__ void k_out(const float* __restrict__ Wout, const float* __restrict__ bout,
                      float* __restrict__ out) {
    __shared__ float s[DD];
    int g = blockIdx.x;
    int t = threadIdx.x;  // 128 threads
    if (t < DD) {
        float c = fmaxf(g_cnt[g], 1.f);
        s[t] = g_pooled[g * DD + t] / c;
    }
    __syncthreads();
    if (t < NT) {
        float acc = bout[t];
#pragma unroll
        for (int k = 0; k < DD; k++) acc = fmaf(s[k], Wout[k * NT + t], acc);
        out[g * NT + t] = acc;
    }
}

// ---------------- host ----------------
extern "C" void kernel_launch(void* const* d_in, const int* in_sizes, int n_in,
                              void* d_out, int out_size) {
    const float* x    = (const float*)d_in[0];
    const float* W1   = (const float*)d_in[1];
    const float* b1   = (const float*)d_in[2];
    const float* W2   = (const float*)d_in[3];
    const float* b2   = (const float*)d_in[4];
    const float* W3   = (const float*)d_in[5];
    const float* b3   = (const float*)d_in[6];
    const float* Wout = (const float*)d_in[7];
    const float* bout = (const float*)d_in[8];
    const int* ei     = (const int*)d_in[9];    // int32: JAX x64 disabled
    const int* bs     = (const int*)d_in[10];   // int32
    float* out = (float*)d_out;

    const int* src = ei;        // edge_index[0]
    const int* dst = ei + NE;   // edge_index[1]

    float *p_h, *p_feat;
    cudaGetSymbolAddress((void**)&p_h, g_h);
    cudaGetSymbolAddress((void**)&p_feat, g_feat);

    const int TB = 256;
    const int gN   = (NN + TB - 1) / TB;
    const int gE   = (NE + TB - 1) / TB;
    const int gN16 = (NN * 16 + TB - 1) / TB;     // 6250
    const int gE16 = NE * 16 / TB;                // 100000
    const int gGemm = NN / 16;                    // 6250

    // graph structure (edge-set invariant across layers)
    k_zero_deg<<<gN, TB>>>();
    k_deg<<<gE, TB>>>(dst);
    k_dinv<<<gN, TB>>>();
    k_norm<<<gE, TB>>>(src, dst);

    // layer 1: relu(gcn(x, W1, b1))
    k_gemm<<<gGemm, TB>>>(x, W1, p_h);
    k_init_agg<<<gN16, TB>>>(b1);
    k_scatter<<<gE16, TB>>>(src, dst);
    k_relu<<<gN16, TB>>>();

    // layer 2: relu(gcn(feat, W2, b2))
    k_gemm<<<gGemm, TB>>>(p_feat, W2, p_h);
    k_init_agg<<<gN16, TB>>>(b2);
    k_scatter<<<gE16, TB>>>(src, dst);
    k_relu<<<gN16, TB>>>();

    // layer 3: gcn(feat, W3, b3) -> stays in g_agg (no relu)
    k_gemm<<<gGemm, TB>>>(p_feat, W3, p_h);
    k_init_agg<<<gN16, TB>>>(b3);
    k_scatter<<<gE16, TB>>>(src, dst);

    // mean pool + output projection
    k_zero_pool<<<(NG * DD + TB - 1) / TB, TB>>>();
    k_count<<<gN, TB>>>(bs);
    k_pool<<<gN16, TB>>>(bs);
    k_out<<<NG, 128>>>(Wout, bout, out);
}

// round 4
// speedup vs baseline: 1.4919x; 1.4919x over previous
#include <cuda_runtime.h>
#include <math.h>

#define NN 100000
#define NE 1600000
#define DD 64
#define NG 512
#define NT 100

#define SCAN_B 1024
#define SCAN_G 98          // ceil(100000/1024)

// ---------------- device scratch (no allocations allowed) ----------------
__device__ __align__(16) float g_h[NN * DD];      // x @ W result
__device__ __align__(16) float g_agg[NN * DD];    // aggregation output (layer result, pre-relu)
__device__ int   g_degi[NN];
__device__ int   g_incl[NN];       // per-block inclusive scan
__device__ int   g_bsum[SCAN_G];
__device__ int   g_bpre[SCAN_G];
__device__ int   g_off[NN + 1];    // CSR row offsets (by dst)
__device__ int   g_cur[NN];        // fill cursors
__device__ float g_dinv[NN];
__device__ __align__(8) int2 g_csr[NE];  // .x = src node, .y = norm bits
__device__ __align__(16) float g_pooled[NG * DD];
__device__ float g_cnt[NG];

__device__ __forceinline__ void red4(float* p, float4 v) {
    asm volatile("red.global.add.v4.f32 [%0], {%1, %2, %3, %4};"
                 :: "l"(p), "f"(v.x), "f"(v.y), "f"(v.z), "f"(v.w)
                 : "memory");
}

// ---------------- zero counters (deg, pool, cnt) ----------------
__global__ void k_zero() {
    int i = blockIdx.x * blockDim.x + threadIdx.x;
    if (i < NN) g_degi[i] = 0;
    if (i < NG * DD) g_pooled[i] = 0.f;
    if (i < NG) g_cnt[i] = 0.f;
}

// ---------------- degree histogram ----------------
__global__ void k_deg(const int* __restrict__ dst) {
    int e = blockIdx.x * blockDim.x + threadIdx.x;
    if (e < NE) atomicAdd(&g_degi[dst[e]], 1);
}

// ---------------- prefix scan (3 kernels) ----------------
__global__ void k_scan1() {
    __shared__ int sh[SCAN_B];
    int i = blockIdx.x * SCAN_B + threadIdx.x;
    int v = (i < NN) ? g_degi[i] : 0;
    sh[threadIdx.x] = v;
    __syncthreads();
#pragma unroll
    for (int ofs = 1; ofs < SCAN_B; ofs <<= 1) {
        int t = (threadIdx.x >= ofs) ? sh[threadIdx.x - ofs] : 0;
        __syncthreads();
        sh[threadIdx.x] += t;
        __syncthreads();
    }
    if (i < NN) g_incl[i] = sh[threadIdx.x];
    if (threadIdx.x == SCAN_B - 1) g_bsum[blockIdx.x] = sh[SCAN_B - 1];
}

__global__ void k_scan2() {
    __shared__ int sh[128];
    int t = threadIdx.x;  // 128 threads
    sh[t] = (t < SCAN_G) ? g_bsum[t] : 0;
    __syncthreads();
#pragma unroll
    for (int ofs = 1; ofs < 128; ofs <<= 1) {
        int v = (t >= ofs) ? sh[t - ofs] : 0;
        __syncthreads();
        sh[t] += v;
        __syncthreads();
    }
    // exclusive prefix for each block
    if (t < SCAN_G) g_bpre[t] = (t == 0) ? 0 : sh[t - 1];
}

__global__ void k_scan3() {
    int i = blockIdx.x * SCAN_B + threadIdx.x;
    if (i < NN) {
        int deg = g_degi[i];
        int off = g_incl[i] - deg + g_bpre[blockIdx.x];  // exclusive
        g_off[i] = off;
        g_cur[i] = off;
        g_dinv[i] = rsqrtf((float)deg + 1.f);
        if (i == NN - 1) g_off[NN] = NE;
    }
}

// ---------------- CSR fill: slot per edge, pack (src, norm) ----------------
__global__ void k_fill(const int* __restrict__ src, const int* __restrict__ dst) {
    int e = blockIdx.x * blockDim.x + threadIdx.x;
    if (e < NE) {
        int s = src[e], d = dst[e];
        int slot = atomicAdd(&g_cur[d], 1);
        float n = g_dinv[s] * g_dinv[d];
        g_csr[slot] = make_int2(s, __float_as_int(n));
    }
}

// ---------------- GEMM: C[n,64] = relu?(A[n,64]) @ W[64,64] ----------------
__global__ void k_gemm(const float* __restrict__ A, const float* __restrict__ W,
                       float* __restrict__ C, int relu) {
    __shared__ float sW[DD * DD];
    __shared__ float sA[16 * DD];
    int tid = threadIdx.x;
    long base = (long)blockIdx.x * 16 * DD;
#pragma unroll
    for (int i = 0; i < 16; i++) sW[tid + i * 256] = W[tid + i * 256];
    if (relu) {
#pragma unroll
        for (int i = 0; i < 4; i++) sA[tid + i * 256] = fmaxf(A[base + tid + i * 256], 0.f);
    } else {
#pragma unroll
        for (int i = 0; i < 4; i++) sA[tid + i * 256] = A[base + tid + i * 256];
    }
    __syncthreads();
    int col = tid & 63;
    int r0 = tid >> 6;  // 0..3
    float a0 = 0.f, a1 = 0.f, a2 = 0.f, a3 = 0.f;
#pragma unroll
    for (int k = 0; k < DD; k++) {
        float w = sW[k * DD + col];
        a0 = fmaf(sA[(r0     ) * DD + k], w, a0);
        a1 = fmaf(sA[(r0 +  4) * DD + k], w, a1);
        a2 = fmaf(sA[(r0 +  8) * DD + k], w, a2);
        a3 = fmaf(sA[(r0 + 12) * DD + k], w, a3);
    }
    C[base + (r0     ) * DD + col] = a0;
    C[base + (r0 +  4) * DD + col] = a1;
    C[base + (r0 +  8) * DD + col] = a2;
    C[base + (r0 + 12) * DD + col] = a3;
}

// ---------------- aggregation (gather, no atomics) ----------------
// agg[i] = sum_{e: dst=i} h[src_e]*norm_e  +  h[i]*dinv_i^2  +  b
// 16 threads per node; each owns a float4 lane group.
__global__ void k_agg(const float* __restrict__ b) {
    int tid = threadIdx.x;
    int node = blockIdx.x * 16 + (tid >> 4);
    int g = tid & 15;
    int start = g_off[node];
    int end   = g_off[node + 1];
    float di = g_dinv[node];
    float d2 = di * di;
    float4 hs = *(const float4*)(g_h + (long)node * DD + g * 4);
    float4 bb = *(const float4*)(b + g * 4);
    float4 a0, a1 = make_float4(0.f, 0.f, 0.f, 0.f);
    a0.x = fmaf(hs.x, d2, bb.x);
    a0.y = fmaf(hs.y, d2, bb.y);
    a0.z = fmaf(hs.z, d2, bb.z);
    a0.w = fmaf(hs.w, d2, bb.w);
    int j = start;
    for (; j + 2 <= end; j += 2) {
        int2 p0 = g_csr[j];
        int2 p1 = g_csr[j + 1];
        float4 h0 = *(const float4*)(g_h + (long)p0.x * DD + g * 4);
        float4 h1 = *(const float4*)(g_h + (long)p1.x * DD + g * 4);
        float n0 = __int_as_float(p0.y);
        float n1 = __int_as_float(p1.y);
        a0.x = fmaf(h0.x, n0, a0.x); a0.y = fmaf(h0.y, n0, a0.y);
        a0.z = fmaf(h0.z, n0, a0.z); a0.w = fmaf(h0.w, n0, a0.w);
        a1.x = fmaf(h1.x, n1, a1.x); a1.y = fmaf(h1.y, n1, a1.y);
        a1.z = fmaf(h1.z, n1, a1.z); a1.w = fmaf(h1.w, n1, a1.w);
    }
    if (j < end) {
        int2 p0 = g_csr[j];
        float4 h0 = *(const float4*)(g_h + (long)p0.x * DD + g * 4);
        float n0 = __int_as_float(p0.y);
        a0.x = fmaf(h0.x, n0, a0.x); a0.y = fmaf(h0.y, n0, a0.y);
        a0.z = fmaf(h0.z, n0, a0.z); a0.w = fmaf(h0.w, n0, a0.w);
    }
    a0.x += a1.x; a0.y += a1.y; a0.z += a1.z; a0.w += a1.w;
    *(float4*)(g_agg + (long)node * DD + g * 4) = a0;
}

// ---------------- pooling ----------------
__global__ void k_count(const int* __restrict__ bs) {
    int i = blockIdx.x * blockDim.x + threadIdx.x;
    if (i < NN) atomicAdd(&g_cnt[bs[i]], 1.f);
}

__global__ void k_pool(const int* __restrict__ bs) {
    int t = blockIdx.x * blockDim.x + threadIdx.x;  // NN*16 threads
    if (t >= NN * 16) return;
    int node = t >> 4, g = t & 15;
    int gr = bs[node];
    float4 v = *(const float4*)(g_agg + (long)node * DD + g * 4);  // layer 3: no relu
    red4(g_pooled + (long)gr * DD + g * 4, v);
}

// ---------------- output projection: out = (pooled/cnt) @ Wout + bout ----
__global__ void k_out(const float* __restrict__ Wout, const float* __restrict__ bout,
                      float* __restrict__ out) {
    __shared__ float s[DD];
    int g = blockIdx.x;
    int t = threadIdx.x;  // 128 threads
    if (t < DD) {
        float c = fmaxf(g_cnt[g], 1.f);
        s[t] = g_pooled[g * DD + t] / c;
    }
    __syncthreads();
    if (t < NT) {
        float acc = bout[t];
#pragma unroll
        for (int k = 0; k < DD; k++) acc = fmaf(s[k], Wout[k * NT + t], acc);
        out[g * NT + t] = acc;
    }
}

// ---------------- host ----------------
extern "C" void kernel_launch(void* const* d_in, const int* in_sizes, int n_in,
                              void* d_out, int out_size) {
    const float* x    = (const float*)d_in[0];
    const float* W1   = (const float*)d_in[1];
    const float* b1   = (const float*)d_in[2];
    const float* W2   = (const float*)d_in[3];
    const float* b2   = (const float*)d_in[4];
    const float* W3   = (const float*)d_in[5];
    const float* b3   = (const float*)d_in[6];
    const float* Wout = (const float*)d_in[7];
    const float* bout = (const float*)d_in[8];
    const int* ei     = (const int*)d_in[9];    // int32 (JAX x64 disabled)
    const int* bs     = (const int*)d_in[10];   // int32
    float* out = (float*)d_out;

    const int* src = ei;        // edge_index[0]
    const int* dst = ei + NE;   // edge_index[1]

    float *p_h, *p_agg;
    cudaGetSymbolAddress((void**)&p_h, g_h);
    cudaGetSymbolAddress((void**)&p_agg, g_agg);

    const int TB = 256;
    const int gN   = (NN + TB - 1) / TB;
    const int gE   = (NE + TB - 1) / TB;
    const int gN16 = (NN * 16 + TB - 1) / TB;     // pool
    const int gAgg = NN / 16;                     // 6250
    const int gGemm = NN / 16;                    // 6250

    // -- structure prep: degree -> offsets -> CSR by dst --
    k_zero<<<gN, TB>>>();
    k_deg<<<gE, TB>>>(dst);
    k_scan1<<<SCAN_G, SCAN_B>>>();
    k_scan2<<<1, 128>>>();
    k_scan3<<<SCAN_G, SCAN_B>>>();
    k_fill<<<gE, TB>>>(src, dst);

    // -- layer 1: agg = A_hat @ (x @ W1) + b1 --
    k_gemm<<<gGemm, TB>>>(x, W1, p_h, 0);
    k_agg<<<gAgg, TB>>>(b1);

    // -- layer 2 (relu fused into gemm A-load) --
    k_gemm<<<gGemm, TB>>>(p_agg, W2, p_h, 1);
    k_agg<<<gAgg, TB>>>(b2);

    // -- layer 3 --
    k_gemm<<<gGemm, TB>>>(p_agg, W3, p_h, 1);
    k_agg<<<gAgg, TB>>>(b3);

    // -- mean pool + output projection --
    k_count<<<gN, TB>>>(bs);
    k_pool<<<gN16, TB>>>(bs);
    k_out<<<NG, 128>>>(Wout, bout, out);
}

// round 5
// speedup vs baseline: 1.5558x; 1.0428x over previous
#include <cuda_runtime.h>
#include <math.h>

#define NN 100000
#define NE 1600000
#define DD 64
#define NG 512
#define NT 100

#define SCAN_B 1024
#define SCAN_G 98          // ceil(100000/1024)

// ---------------- device scratch (no allocations allowed) ----------------
__device__ __align__(16) float g_h[NN * DD];      // x @ W result
__device__ __align__(16) float g_agg[NN * DD];    // aggregation output (pre-relu)
__device__ int   g_degi[NN];
__device__ int   g_incl[NN];
__device__ int   g_bsum[SCAN_G];
__device__ int   g_bpre[SCAN_G];
__device__ int   g_off[NN + 1];    // CSR row offsets (by dst)
__device__ int   g_cur[NN];
__device__ float g_dinv[NN];
__device__ __align__(8) int2 g_csr[NE];  // .x = src node, .y = norm bits
__device__ __align__(16) float g_pooled[NG * DD];
__device__ int   g_cnti[NG];
__device__ int   g_gs[NG];         // per-graph start row (batch_seg is sorted)

// ---------------- zero counters ----------------
__global__ void k_zero() {
    int i = blockIdx.x * blockDim.x + threadIdx.x;
    if (i < NN) g_degi[i] = 0;
    if (i < NG) g_cnti[i] = 0;
}

// ---------------- degree histogram ----------------
__global__ void k_deg(const int* __restrict__ dst) {
    int e = blockIdx.x * blockDim.x + threadIdx.x;
    if (e < NE) atomicAdd(&g_degi[dst[e]], 1);
}

// ---------------- prefix scan (3 kernels) ----------------
__global__ void k_scan1() {
    __shared__ int sh[SCAN_B];
    int i = blockIdx.x * SCAN_B + threadIdx.x;
    int v = (i < NN) ? g_degi[i] : 0;
    sh[threadIdx.x] = v;
    __syncthreads();
#pragma unroll
    for (int ofs = 1; ofs < SCAN_B; ofs <<= 1) {
        int t = (threadIdx.x >= ofs) ? sh[threadIdx.x - ofs] : 0;
        __syncthreads();
        sh[threadIdx.x] += t;
        __syncthreads();
    }
    if (i < NN) g_incl[i] = sh[threadIdx.x];
    if (threadIdx.x == SCAN_B - 1) g_bsum[blockIdx.x] = sh[SCAN_B - 1];
}

__global__ void k_scan2() {
    __shared__ int sh[128];
    int t = threadIdx.x;  // 128 threads
    sh[t] = (t < SCAN_G) ? g_bsum[t] : 0;
    __syncthreads();
#pragma unroll
    for (int ofs = 1; ofs < 128; ofs <<= 1) {
        int v = (t >= ofs) ? sh[t - ofs] : 0;
        __syncthreads();
        sh[t] += v;
        __syncthreads();
    }
    if (t < SCAN_G) g_bpre[t] = (t == 0) ? 0 : sh[t - 1];
}

__global__ void k_scan3() {
    int i = blockIdx.x * SCAN_B + threadIdx.x;
    if (i < NN) {
        int deg = g_degi[i];
        int off = g_incl[i] - deg + g_bpre[blockIdx.x];  // exclusive
        g_off[i] = off;
        g_cur[i] = off;
        g_dinv[i] = rsqrtf((float)deg + 1.f);
        if (i == NN - 1) g_off[NN] = NE;
    }
}

// ---------------- CSR fill ----------------
__global__ void k_fill(const int* __restrict__ src, const int* __restrict__ dst) {
    int e = blockIdx.x * blockDim.x + threadIdx.x;
    if (e < NE) {
        int s = src[e], d = dst[e];
        int slot = atomicAdd(&g_cur[d], 1);
        float n = g_dinv[s] * g_dinv[d];
        g_csr[slot] = make_int2(s, __float_as_int(n));
    }
}

// ---------------- GEMM: C[n,64] = relu?(A[n,64]) @ W[64,64] ----------------
__global__ void k_gemm(const float* __restrict__ A, const float* __restrict__ W,
                       float* __restrict__ C, int relu) {
    __shared__ float sW[DD * DD];
    __shared__ float sA[16 * DD];
    int tid = threadIdx.x;
    long base = (long)blockIdx.x * 16 * DD;
#pragma unroll
    for (int i = 0; i < 16; i++) sW[tid + i * 256] = W[tid + i * 256];
    if (relu) {
#pragma unroll
        for (int i = 0; i < 4; i++) sA[tid + i * 256] = fmaxf(A[base + tid + i * 256], 0.f);
    } else {
#pragma unroll
        for (int i = 0; i < 4; i++) sA[tid + i * 256] = A[base + tid + i * 256];
    }
    __syncthreads();
    int col = tid & 63;
    int r0 = tid >> 6;  // 0..3
    float a0 = 0.f, a1 = 0.f, a2 = 0.f, a3 = 0.f;
#pragma unroll
    for (int k = 0; k < DD; k++) {
        float w = sW[k * DD + col];
        a0 = fmaf(sA[(r0     ) * DD + k], w, a0);
        a1 = fmaf(sA[(r0 +  4) * DD + k], w, a1);
        a2 = fmaf(sA[(r0 +  8) * DD + k], w, a2);
        a3 = fmaf(sA[(r0 + 12) * DD + k], w, a3);
    }
    C[base + (r0     ) * DD + col] = a0;
    C[base + (r0 +  4) * DD + col] = a1;
    C[base + (r0 +  8) * DD + col] = a2;
    C[base + (r0 + 12) * DD + col] = a3;
}

// ---------------- aggregation (gather, no atomics, MLP=4) ----------------
__global__ void k_agg(const float* __restrict__ b) {
    int tid = threadIdx.x;
    int node = blockIdx.x * 16 + (tid >> 4);
    int g = tid & 15;
    int start = g_off[node];
    int end   = g_off[node + 1];
    float di = g_dinv[node];
    float d2 = di * di;
    float4 hs = *(const float4*)(g_h + (long)node * DD + g * 4);
    float4 bb = *(const float4*)(b + g * 4);
    float4 a0, a1, a2, a3;
    a0.x = fmaf(hs.x, d2, bb.x);
    a0.y = fmaf(hs.y, d2, bb.y);
    a0.z = fmaf(hs.z, d2, bb.z);
    a0.w = fmaf(hs.w, d2, bb.w);
    a1 = make_float4(0.f, 0.f, 0.f, 0.f);
    a2 = a1; a3 = a1;
    int j = start;
    for (; j + 4 <= end; j += 4) {
        int2 p0 = g_csr[j];
        int2 p1 = g_csr[j + 1];
        int2 p2 = g_csr[j + 2];
        int2 p3 = g_csr[j + 3];
        float4 h0 = *(const float4*)(g_h + (long)p0.x * DD + g * 4);
        float4 h1 = *(const float4*)(g_h + (long)p1.x * DD + g * 4);
        float4 h2 = *(const float4*)(g_h + (long)p2.x * DD + g * 4);
        float4 h3 = *(const float4*)(g_h + (long)p3.x * DD + g * 4);
        float n0 = __int_as_float(p0.y);
        float n1 = __int_as_float(p1.y);
        float n2 = __int_as_float(p2.y);
        float n3 = __int_as_float(p3.y);
        a0.x = fmaf(h0.x, n0, a0.x); a0.y = fmaf(h0.y, n0, a0.y);
        a0.z = fmaf(h0.z, n0, a0.z); a0.w = fmaf(h0.w, n0, a0.w);
        a1.x = fmaf(h1.x, n1, a1.x); a1.y = fmaf(h1.y, n1, a1.y);
        a1.z = fmaf(h1.z, n1, a1.z); a1.w = fmaf(h1.w, n1, a1.w);
        a2.x = fmaf(h2.x, n2, a2.x); a2.y = fmaf(h2.y, n2, a2.y);
        a2.z = fmaf(h2.z, n2, a2.z); a2.w = fmaf(h2.w, n2, a2.w);
        a3.x = fmaf(h3.x, n3, a3.x); a3.y = fmaf(h3.y, n3, a3.y);
        a3.z = fmaf(h3.z, n3, a3.z); a3.w = fmaf(h3.w, n3, a3.w);
    }
    for (; j < end; j++) {
        int2 p0 = g_csr[j];
        float4 h0 = *(const float4*)(g_h + (long)p0.x * DD + g * 4);
        float n0 = __int_as_float(p0.y);
        a0.x = fmaf(h0.x, n0, a0.x); a0.y = fmaf(h0.y, n0, a0.y);
        a0.z = fmaf(h0.z, n0, a0.z); a0.w = fmaf(h0.w, n0, a0.w);
    }
    a0.x += a1.x + a2.x + a3.x;
    a0.y += a1.y + a2.y + a3.y;
    a0.z += a1.z + a2.z + a3.z;
    a0.w += a1.w + a2.w + a3.w;
    *(float4*)(g_agg + (long)node * DD + g * 4) = a0;
}

// ---------------- pooling (batch_seg sorted -> contiguous segments) ----------------
__global__ void k_count(const int* __restrict__ bs) {
    int i = blockIdx.x * blockDim.x + threadIdx.x;
    if (i < NN) atomicAdd(&g_cnti[bs[i]], 1);
}

__global__ void k_gstart() {   // 1 block, 512 threads: exclusive scan of counts
    __shared__ int sh[NG];
    int t = threadIdx.x;
    int c = g_cnti[t];
    sh[t] = c;
    __syncthreads();
#pragma unroll
    for (int ofs = 1; ofs < NG; ofs <<= 1) {
        int v = (t >= ofs) ? sh[t - ofs] : 0;
        __syncthreads();
        sh[t] += v;
        __syncthreads();
    }
    g_gs[t] = sh[t] - c;   // exclusive
}

// one block per graph: mean over its contiguous node range (no atomics)
__global__ void k_pool() {
    __shared__ float sh[256];
    int gr = blockIdx.x;
    int tid = threadIdx.x;         // 256
    int s = g_gs[gr];
    int cnt = g_cnti[gr];
    int c = tid & 63;
    int ro = tid >> 6;             // 0..3
    float acc = 0.f;
    for (int r = s + ro; r < s + cnt; r += 4)
        acc += g_agg[(long)r * DD + c];
    sh[tid] = acc;
    __syncthreads();
    if (ro == 0) {
        float v = sh[c] + sh[c + 64] + sh[c + 128] + sh[c + 192];
        g_pooled[gr * DD + c] = v / fmaxf((float)cnt, 1.f);
    }
}

// ---------------- output projection: out = pooled @ Wout + bout ----------------
__global__ void k_out(const float* __restrict__ Wout, const float* __restrict__ bout,
                      float* __restrict__ out) {
    __shared__ float s[DD];
    int g = blockIdx.x;
    int t = threadIdx.x;  // 128 threads
    if (t < DD) s[t] = g_pooled[g * DD + t];
    __syncthreads();
    if (t < NT) {
        float acc = bout[t];
#pragma unroll
        for (int k = 0; k < DD; k++) acc = fmaf(s[k], Wout[k * NT + t], acc);
        out[g * NT + t] = acc;
    }
}

// ---------------- host ----------------
extern "C" void kernel_launch(void* const* d_in, const int* in_sizes, int n_in,
                              void* d_out, int out_size) {
    const float* x    = (const float*)d_in[0];
    const float* W1   = (const float*)d_in[1];
    const float* b1   = (const float*)d_in[2];
    const float* W2   = (const float*)d_in[3];
    const float* b2   = (const float*)d_in[4];
    const float* W3   = (const float*)d_in[5];
    const float* b3   = (const float*)d_in[6];
    const float* Wout = (const float*)d_in[7];
    const float* bout = (const float*)d_in[8];
    const int* ei     = (const int*)d_in[9];    // int32 (JAX x64 disabled)
    const int* bs     = (const int*)d_in[10];   // int32
    float* out = (float*)d_out;

    const int* src = ei;        // edge_index[0]
    const int* dst = ei + NE;   // edge_index[1]

    float *p_h, *p_agg;
    cudaGetSymbolAddress((void**)&p_h, g_h);
    cudaGetSymbolAddress((void**)&p_agg, g_agg);

    const int TB = 256;
    const int gN   = (NN + TB - 1) / TB;
    const int gE   = (NE + TB - 1) / TB;
    const int gAgg = NN / 16;                     // 6250
    const int gGemm = NN / 16;                    // 6250

    // -- structure prep: degree -> offsets -> CSR by dst; graph segments --
    k_zero<<<gN, TB>>>();
    k_deg<<<gE, TB>>>(dst);
    k_scan1<<<SCAN_G, SCAN_B>>>();
    k_scan2<<<1, 128>>>();
    k_scan3<<<SCAN_G, SCAN_B>>>();
    k_fill<<<gE, TB>>>(src, dst);
    k_count<<<gN, TB>>>(bs);
    k_gstart<<<1, NG>>>();

    // -- layer 1: agg = A_hat @ (x @ W1) + b1 --
    k_gemm<<<gGemm, TB>>>(x, W1, p_h, 0);
    k_agg<<<gAgg, TB>>>(b1);

    // -- layer 2 (relu fused into gemm A-load) --
    k_gemm<<<gGemm, TB>>>(p_agg, W2, p_h, 1);
    k_agg<<<gAgg, TB>>>(b2);

    // -- layer 3 --
    k_gemm<<<gGemm, TB>>>(p_agg, W3, p_h, 1);
    k_agg<<<gAgg, TB>>>(b3);

    // -- mean pool (segmented, no atomics) + output projection --
    k_pool<<<NG, 256>>>();
    k_out<<<NG, 128>>>(Wout, bout, out);
}

// round 6
// speedup vs baseline: 1.6226x; 1.0430x over previous
#include <cuda_runtime.h>
#include <cuda_fp16.h>
#include <math.h>

#define NN 100000
#define NE 1600000
#define DD 64
#define NG 512
#define NT 100

#define SCAN_B 1024
#define SCAN_G 98          // ceil(100000/1024)

// ---------------- device scratch (no allocations allowed) ----------------
__device__ __align__(16) unsigned int g_hh[NN * 32];  // h in half2: 64 halves = 128B/row
__device__ __align__(16) float g_agg[NN * DD];        // aggregation output (pre-relu, fp32)
__device__ int   g_degi[NN];
__device__ int   g_incl[NN];
__device__ int   g_bsum[SCAN_G];
__device__ int   g_bpre[SCAN_G];
__device__ int   g_off[NN + 1];    // CSR row offsets (by dst)
__device__ int   g_cur[NN];
__device__ float g_dinv[NN];
__device__ __align__(8) int2 g_csr[NE];  // .x = src node, .y = norm bits
__device__ __align__(16) float g_pooled[NG * DD];
__device__ int   g_cnti[NG];
__device__ int   g_gs[NG];         // per-graph start row (batch_seg sorted)

// ---------------- zero counters ----------------
__global__ void k_zero() {
    int i = blockIdx.x * blockDim.x + threadIdx.x;
    if (i < NN) g_degi[i] = 0;
    if (i < NG) g_cnti[i] = 0;
}

// ---------------- degree histogram ----------------
__global__ void k_deg(const int* __restrict__ dst) {
    int e = blockIdx.x * blockDim.x + threadIdx.x;
    if (e < NE) atomicAdd(&g_degi[dst[e]], 1);
}

// ---------------- prefix scan (3 kernels) ----------------
__global__ void k_scan1() {
    __shared__ int sh[SCAN_B];
    int i = blockIdx.x * SCAN_B + threadIdx.x;
    int v = (i < NN) ? g_degi[i] : 0;
    sh[threadIdx.x] = v;
    __syncthreads();
#pragma unroll
    for (int ofs = 1; ofs < SCAN_B; ofs <<= 1) {
        int t = (threadIdx.x >= ofs) ? sh[threadIdx.x - ofs] : 0;
        __syncthreads();
        sh[threadIdx.x] += t;
        __syncthreads();
    }
    if (i < NN) g_incl[i] = sh[threadIdx.x];
    if (threadIdx.x == SCAN_B - 1) g_bsum[blockIdx.x] = sh[SCAN_B - 1];
}

__global__ void k_scan2() {
    __shared__ int sh[128];
    int t = threadIdx.x;  // 128 threads
    sh[t] = (t < SCAN_G) ? g_bsum[t] : 0;
    __syncthreads();
#pragma unroll
    for (int ofs = 1; ofs < 128; ofs <<= 1) {
        int v = (t >= ofs) ? sh[t - ofs] : 0;
        __syncthreads();
        sh[t] += v;
        __syncthreads();
    }
    if (t < SCAN_G) g_bpre[t] = (t == 0) ? 0 : sh[t - 1];
}

__global__ void k_scan3() {
    int i = blockIdx.x * SCAN_B + threadIdx.x;
    if (i < NN) {
        int deg = g_degi[i];
        int off = g_incl[i] - deg + g_bpre[blockIdx.x];  // exclusive
        g_off[i] = off;
        g_cur[i] = off;
        g_dinv[i] = rsqrtf((float)deg + 1.f);
        if (i == NN - 1) g_off[NN] = NE;
    }
}

// ---------------- CSR fill ----------------
__global__ void k_fill(const int* __restrict__ src, const int* __restrict__ dst) {
    int e = blockIdx.x * blockDim.x + threadIdx.x;
    if (e < NE) {
        int s = src[e], d = dst[e];
        int slot = atomicAdd(&g_cur[d], 1);
        float n = g_dinv[s] * g_dinv[d];
        g_csr[slot] = make_int2(s, __float_as_int(n));
    }
}

// ---------------- GEMM: Ch[n,64](fp16) = relu?(A[n,64]) @ W[64,64] ----------------
// 256 threads, 16 rows/block. Each thread: 2 adjacent cols x 2 rows -> packs half2.
__global__ void k_gemm(const float* __restrict__ A, const float* __restrict__ W,
                       unsigned int* __restrict__ Ch, int relu) {
    __shared__ float sW[DD * DD];
    __shared__ float sA[16 * DD];
    int tid = threadIdx.x;
    long base = (long)blockIdx.x * 16 * DD;
#pragma unroll
    for (int i = 0; i < 16; i++) sW[tid + i * 256] = W[tid + i * 256];
    if (relu) {
#pragma unroll
        for (int i = 0; i < 4; i++) sA[tid + i * 256] = fmaxf(A[base + tid + i * 256], 0.f);
    } else {
#pragma unroll
        for (int i = 0; i < 4; i++) sA[tid + i * 256] = A[base + tid + i * 256];
    }
    __syncthreads();
    int c = (tid & 31) * 2;   // 0,2,...,62
    int r = tid >> 5;         // 0..7
    float a00 = 0.f, a01 = 0.f, a10 = 0.f, a11 = 0.f;
#pragma unroll
    for (int k = 0; k < DD; k++) {
        float w0 = sW[k * DD + c];
        float w1 = sW[k * DD + c + 1];
        float x0 = sA[r * DD + k];
        float x1 = sA[(r + 8) * DD + k];
        a00 = fmaf(x0, w0, a00); a01 = fmaf(x0, w1, a01);
        a10 = fmaf(x1, w0, a10); a11 = fmaf(x1, w1, a11);
    }
    long row0 = (long)blockIdx.x * 16 + r;
    long row1 = row0 + 8;
    __half2 p0 = __floats2half2_rn(a00, a01);
    __half2 p1 = __floats2half2_rn(a10, a11);
    Ch[row0 * 32 + (c >> 1)] = *(unsigned int*)&p0;
    Ch[row1 * 32 + (c >> 1)] = *(unsigned int*)&p1;
}

// ---------------- aggregation (gather fp16 rows, no atomics, MLP=4) ----------------
__device__ __forceinline__ float4 h4_load(const uint2* __restrict__ hh, long idx) {
    uint2 v = hh[idx];
    __half2 lo = *(__half2*)&v.x;
    __half2 hi = *(__half2*)&v.y;
    float2 f0 = __half22float2(lo);
    float2 f1 = __half22float2(hi);
    return make_float4(f0.x, f0.y, f1.x, f1.y);
}

__global__ void k_agg(const float* __restrict__ b) {
    const uint2* hh = (const uint2*)g_hh;   // 16 uint2 per row
    int tid = threadIdx.x;
    int node = blockIdx.x * 16 + (tid >> 4);
    int g = tid & 15;
    int start = g_off[node];
    int end   = g_off[node + 1];
    float di = g_dinv[node];
    float d2 = di * di;
    float4 hs = h4_load(hh, (long)node * 16 + g);
    float4 bb = *(const float4*)(b + g * 4);
    float4 a0, a1, a2, a3;
    a0.x = fmaf(hs.x, d2, bb.x);
    a0.y = fmaf(hs.y, d2, bb.y);
    a0.z = fmaf(hs.z, d2, bb.z);
    a0.w = fmaf(hs.w, d2, bb.w);
    a1 = make_float4(0.f, 0.f, 0.f, 0.f);
    a2 = a1; a3 = a1;
    int j = start;
    for (; j + 4 <= end; j += 4) {
        int2 p0 = g_csr[j];
        int2 p1 = g_csr[j + 1];
        int2 p2 = g_csr[j + 2];
        int2 p3 = g_csr[j + 3];
        float4 h0 = h4_load(hh, (long)p0.x * 16 + g);
        float4 h1 = h4_load(hh, (long)p1.x * 16 + g);
        float4 h2 = h4_load(hh, (long)p2.x * 16 + g);
        float4 h3 = h4_load(hh, (long)p3.x * 16 + g);
        float n0 = __int_as_float(p0.y);
        float n1 = __int_as_float(p1.y);
        float n2 = __int_as_float(p2.y);
        float n3 = __int_as_float(p3.y);
        a0.x = fmaf(h0.x, n0, a0.x); a0.y = fmaf(h0.y, n0, a0.y);
        a0.z = fmaf(h0.z, n0, a0.z); a0.w = fmaf(h0.w, n0, a0.w);
        a1.x = fmaf(h1.x, n1, a1.x); a1.y = fmaf(h1.y, n1, a1.y);
        a1.z = fmaf(h1.z, n1, a1.z); a1.w = fmaf(h1.w, n1, a1.w);
        a2.x = fmaf(h2.x, n2, a2.x); a2.y = fmaf(h2.y, n2, a2.y);
        a2.z = fmaf(h2.z, n2, a2.z); a2.w = fmaf(h2.w, n2, a2.w);
        a3.x = fmaf(h3.x, n3, a3.x); a3.y = fmaf(h3.y, n3, a3.y);
        a3.z = fmaf(h3.z, n3, a3.z); a3.w = fmaf(h3.w, n3, a3.w);
    }
    for (; j < end; j++) {
        int2 p0 = g_csr[j];
        float4 h0 = h4_load(hh, (long)p0.x * 16 + g);
        float n0 = __int_as_float(p0.y);
        a0.x = fmaf(h0.x, n0, a0.x); a0.y = fmaf(h0.y, n0, a0.y);
        a0.z = fmaf(h0.z, n0, a0.z); a0.w = fmaf(h0.w, n0, a0.w);
    }
    a0.x += a1.x + a2.x + a3.x;
    a0.y += a1.y + a2.y + a3.y;
    a0.z += a1.z + a2.z + a3.z;
    a0.w += a1.w + a2.w + a3.w;
    *(float4*)(g_agg + (long)node * DD + g * 4) = a0;
}

// ---------------- pooling (batch_seg sorted -> contiguous segments) ----------------
__global__ void k_count(const int* __restrict__ bs) {
    int i = blockIdx.x * blockDim.x + threadIdx.x;
    if (i < NN) atomicAdd(&g_cnti[bs[i]], 1);
}

__global__ void k_gstart() {   // 1 block, 512 threads: exclusive scan of counts
    __shared__ int sh[NG];
    int t = threadIdx.x;
    int c = g_cnti[t];
    sh[t] = c;
    __syncthreads();
#pragma unroll
    for (int ofs = 1; ofs < NG; ofs <<= 1) {
        int v = (t >= ofs) ? sh[t - ofs] : 0;
        __syncthreads();
        sh[t] += v;
        __syncthreads();
    }
    g_gs[t] = sh[t] - c;   // exclusive
}

// one block per graph: mean over its contiguous node range (no atomics)
__global__ void k_pool() {
    __shared__ float sh[256];
    int gr = blockIdx.x;
    int tid = threadIdx.x;         // 256
    int s = g_gs[gr];
    int cnt = g_cnti[gr];
    int c = tid & 63;
    int ro = tid >> 6;             // 0..3
    float acc = 0.f;
    for (int r = s + ro; r < s + cnt; r += 4)
        acc += g_agg[(long)r * DD + c];
    sh[tid] = acc;
    __syncthreads();
    if (ro == 0) {
        float v = sh[c] + sh[c + 64] + sh[c + 128] + sh[c + 192];
        g_pooled[gr * DD + c] = v / fmaxf((float)cnt, 1.f);
    }
}

// ---------------- output projection: out = pooled @ Wout + bout ----------------
__global__ void k_out(const float* __restrict__ Wout, const float* __restrict__ bout,
                      float* __restrict__ out) {
    __shared__ float s[DD];
    int g = blockIdx.x;
    int t = threadIdx.x;  // 128 threads
    if (t < DD) s[t] = g_pooled[g * DD + t];
    __syncthreads();
    if (t < NT) {
        float acc = bout[t];
#pragma unroll
        for (int k = 0; k < DD; k++) acc = fmaf(s[k], Wout[k * NT + t], acc);
        out[g * NT + t] = acc;
    }
}

// ---------------- host ----------------
extern "C" void kernel_launch(void* const* d_in, const int* in_sizes, int n_in,
                              void* d_out, int out_size) {
    const float* x    = (const float*)d_in[0];
    const float* W1   = (const float*)d_in[1];
    const float* b1   = (const float*)d_in[2];
    const float* W2   = (const float*)d_in[3];
    const float* b2   = (const float*)d_in[4];
    const float* W3   = (const float*)d_in[5];
    const float* b3   = (const float*)d_in[6];
    const float* Wout = (const float*)d_in[7];
    const float* bout = (const float*)d_in[8];
    const int* ei     = (const int*)d_in[9];    // int32 (JAX x64 disabled)
    const int* bs     = (const int*)d_in[10];   // int32
    float* out = (float*)d_out;

    const int* src = ei;        // edge_index[0]
    const int* dst = ei + NE;   // edge_index[1]

    unsigned int* p_hh;
    float* p_agg;
    cudaGetSymbolAddress((void**)&p_hh, g_hh);
    cudaGetSymbolAddress((void**)&p_agg, g_agg);

    const int TB = 256;
    const int gN   = (NN + TB - 1) / TB;
    const int gE   = (NE + TB - 1) / TB;
    const int gAgg = NN / 16;                     // 6250
    const int gGemm = NN / 16;                    // 6250

    // -- structure prep: degree -> offsets -> CSR by dst; graph segments --
    k_zero<<<gN, TB>>>();
    k_deg<<<gE, TB>>>(dst);
    k_scan1<<<SCAN_G, SCAN_B>>>();
    k_scan2<<<1, 128>>>();
    k_scan3<<<SCAN_G, SCAN_B>>>();
    k_fill<<<gE, TB>>>(src, dst);
    k_count<<<gN, TB>>>(bs);
    k_gstart<<<1, NG>>>();

    // -- layer 1: agg = A_hat @ (x @ W1) + b1 --
    k_gemm<<<gGemm, TB>>>(x, W1, p_hh, 0);
    k_agg<<<gAgg, TB>>>(b1);

    // -- layer 2 (relu fused into gemm A-load) --
    k_gemm<<<gGemm, TB>>>(p_agg, W2, p_hh, 1);
    k_agg<<<gAgg, TB>>>(b2);

    // -- layer 3 --
    k_gemm<<<gGemm, TB>>>(p_agg, W3, p_hh, 1);
    k_agg<<<gAgg, TB>>>(b3);

    // -- mean pool (segmented, no atomics) + output projection --
    k_pool<<<NG, 256>>>();
    k_out<<<NG, 128>>>(Wout, bout, out);
}

// round 7
// speedup vs baseline: 2.1370x; 1.3170x over previous
#include <cuda_runtime.h>
#include <cuda_fp16.h>
#include <math.h>

#define NN 100000
#define NE 1600000
#define DD 64
#define NG 512
#define NT 100

#define SCAN_B 1024
#define SCAN_G 98          // ceil(100000/1024)

// ---------------- device scratch (no allocations allowed) ----------------
__device__ __align__(16) unsigned int g_hh[NN * 32];  // h in half2: 64 halves = 128B/row
__device__ __align__(16) float g_agg[NN * DD];        // aggregation output (pre-relu, fp32)
__device__ int   g_degi[NN];
__device__ int   g_incl[NN];
__device__ int   g_bsum[SCAN_G];
__device__ int   g_off[NN + 1];    // CSR row offsets (by dst)
__device__ int   g_cur[NN];
__device__ float g_dinv[NN];
__device__ __align__(8) int2 g_csr[NE];  // .x = src node, .y = norm bits

// ---------------- zero degree ----------------
__global__ void k_zero() {
    int i = blockIdx.x * blockDim.x + threadIdx.x;
    if (i < NN) g_degi[i] = 0;
}

// ---------------- degree histogram ----------------
__global__ void k_deg(const int* __restrict__ dst) {
    int e = blockIdx.x * blockDim.x + threadIdx.x;
    if (e < NE) atomicAdd(&g_degi[dst[e]], 1);
}

// ---------------- prefix scan (2 kernels) ----------------
__global__ void k_scan1() {
    __shared__ int sh[SCAN_B];
    int i = blockIdx.x * SCAN_B + threadIdx.x;
    int v = (i < NN) ? g_degi[i] : 0;
    sh[threadIdx.x] = v;
    __syncthreads();
#pragma unroll
    for (int ofs = 1; ofs < SCAN_B; ofs <<= 1) {
        int t = (threadIdx.x >= ofs) ? sh[threadIdx.x - ofs] : 0;
        __syncthreads();
        sh[threadIdx.x] += t;
        __syncthreads();
    }
    if (i < NN) g_incl[i] = sh[threadIdx.x];
    if (threadIdx.x == SCAN_B - 1) g_bsum[blockIdx.x] = sh[SCAN_B - 1];
}

// merged: each block redundantly scans the 98 block sums, then applies.
__global__ void k_scan3() {
    __shared__ int sb[128];
    int t = threadIdx.x;
    if (t < 128) sb[t] = (t < SCAN_G) ? g_bsum[t] : 0;
    __syncthreads();
#pragma unroll
    for (int ofs = 1; ofs < 128; ofs <<= 1) {
        int v = (t < 128 && t >= ofs) ? sb[t - ofs] : 0;
        __syncthreads();
        if (t < 128) sb[t] += v;
        __syncthreads();
    }
    int bpre = (blockIdx.x == 0) ? 0 : sb[blockIdx.x - 1];
    int i = blockIdx.x * SCAN_B + t;
    if (i < NN) {
        int deg = g_degi[i];
        int off = g_incl[i] - deg + bpre;  // exclusive
        g_off[i] = off;
        g_cur[i] = off;
        g_dinv[i] = rsqrtf((float)deg + 1.f);
        if (i == NN - 1) g_off[NN] = NE;
    }
}

// ---------------- CSR fill ----------------
__global__ void k_fill(const int* __restrict__ src, const int* __restrict__ dst) {
    int e = blockIdx.x * blockDim.x + threadIdx.x;
    if (e < NE) {
        int s = src[e], d = dst[e];
        int slot = atomicAdd(&g_cur[d], 1);
        float n = g_dinv[s] * g_dinv[d];
        g_csr[slot] = make_int2(s, __float_as_int(n));
    }
}

// ---------------- GEMM: Ch[n,64](fp16) = relu?(A[n,64]) @ W[64,64] ----------------
// 256 threads, 64 rows/block, 4x4 register tile per thread (FMA-floor bound).
__global__ void k_gemm(const float* __restrict__ A, const float* __restrict__ W,
                       unsigned int* __restrict__ Ch, int relu) {
    __shared__ float sW[DD * DD];
    __shared__ float sA[DD * DD];
    int tid = threadIdx.x;
    int rbase = blockIdx.x * 64;

    const float4* W4 = (const float4*)W;
    float4* sW4 = (float4*)sW;
#pragma unroll
    for (int i = 0; i < 4; i++) sW4[tid + i * 256] = W4[tid + i * 256];

    const float4* A4 = (const float4*)A;
    float4* sA4 = (float4*)sA;
#pragma unroll
    for (int i = 0; i < 4; i++) {
        int idx = tid + i * 256;          // 0..1023
        int r = rbase + (idx >> 4);
        float4 v = make_float4(0.f, 0.f, 0.f, 0.f);
        if (r < NN) v = A4[(long)r * 16 + (idx & 15)];
        if (relu) {
            v.x = fmaxf(v.x, 0.f); v.y = fmaxf(v.y, 0.f);
            v.z = fmaxf(v.z, 0.f); v.w = fmaxf(v.w, 0.f);
        }
        sA4[idx] = v;
    }
    __syncthreads();

    int tx = tid & 15;        // col group: cols 4*tx .. 4*tx+3
    int ty = tid >> 4;        // row group: rows 4*ty .. 4*ty+3
    int c0 = tx * 4;
    int r0 = ty * 4;
    float acc[4][4] = {{0.f}};
#pragma unroll 4
    for (int k = 0; k < DD; k++) {
        float4 w = *(const float4*)&sW[k * DD + c0];
        float a0 = sA[(r0 + 0) * DD + k];
        float a1 = sA[(r0 + 1) * DD + k];
        float a2 = sA[(r0 + 2) * DD + k];
        float a3 = sA[(r0 + 3) * DD + k];
        acc[0][0] = fmaf(a0, w.x, acc[0][0]); acc[0][1] = fmaf(a0, w.y, acc[0][1]);
        acc[0][2] = fmaf(a0, w.z, acc[0][2]); acc[0][3] = fmaf(a0, w.w, acc[0][3]);
        acc[1][0] = fmaf(a1, w.x, acc[1][0]); acc[1][1] = fmaf(a1, w.y, acc[1][1]);
        acc[1][2] = fmaf(a1, w.z, acc[1][2]); acc[1][3] = fmaf(a1, w.w, acc[1][3]);
        acc[2][0] = fmaf(a2, w.x, acc[2][0]); acc[2][1] = fmaf(a2, w.y, acc[2][1]);
        acc[2][2] = fmaf(a2, w.z, acc[2][2]); acc[2][3] = fmaf(a2, w.w, acc[2][3]);
        acc[3][0] = fmaf(a3, w.x, acc[3][0]); acc[3][1] = fmaf(a3, w.y, acc[3][1]);
        acc[3][2] = fmaf(a3, w.z, acc[3][2]); acc[3][3] = fmaf(a3, w.w, acc[3][3]);
    }

#pragma unroll
    for (int i = 0; i < 4; i++) {
        int r = rbase + r0 + i;
        if (r < NN) {
            __half2 lo = __floats2half2_rn(acc[i][0], acc[i][1]);
            __half2 hi = __floats2half2_rn(acc[i][2], acc[i][3]);
            uint2 p = make_uint2(*(unsigned int*)&lo, *(unsigned int*)&hi);
            *(uint2*)&Ch[(long)r * 32 + tx * 2] = p;
        }
    }
}

// ---------------- aggregation (gather fp16 rows, no atomics, MLP=4) ----------------
__device__ __forceinline__ float4 h4_load(const uint2* __restrict__ hh, int idx) {
    uint2 v = hh[idx];
    __half2 lo = *(__half2*)&v.x;
    __half2 hi = *(__half2*)&v.y;
    float2 f0 = __half22float2(lo);
    float2 f1 = __half22float2(hi);
    return make_float4(f0.x, f0.y, f1.x, f1.y);
}

__global__ void k_agg(const float* __restrict__ b) {
    const uint2* hh = (const uint2*)g_hh;   // 16 uint2 per row
    int tid = threadIdx.x;
    int node = blockIdx.x * 16 + (tid >> 4);
    int g = tid & 15;
    int start = g_off[node];
    int end   = g_off[node + 1];
    float di = g_dinv[node];
    float d2 = di * di;
    float4 hs = h4_load(hh, node * 16 + g);
    float4 bb = *(const float4*)(b + g * 4);
    float4 a0, a1, a2, a3;
    a0.x = fmaf(hs.x, d2, bb.x);
    a0.y = fmaf(hs.y, d2, bb.y);
    a0.z = fmaf(hs.z, d2, bb.z);
    a0.w = fmaf(hs.w, d2, bb.w);
    a1 = make_float4(0.f, 0.f, 0.f, 0.f);
    a2 = a1; a3 = a1;
    int j = start;
    for (; j + 4 <= end; j += 4) {
        int2 p0 = g_csr[j];
        int2 p1 = g_csr[j + 1];
        int2 p2 = g_csr[j + 2];
        int2 p3 = g_csr[j + 3];
        float4 h0 = h4_load(hh, p0.x * 16 + g);
        float4 h1 = h4_load(hh, p1.x * 16 + g);
        float4 h2 = h4_load(hh, p2.x * 16 + g);
        float4 h3 = h4_load(hh, p3.x * 16 + g);
        float n0 = __int_as_float(p0.y);
        float n1 = __int_as_float(p1.y);
        float n2 = __int_as_float(p2.y);
        float n3 = __int_as_float(p3.y);
        a0.x = fmaf(h0.x, n0, a0.x); a0.y = fmaf(h0.y, n0, a0.y);
        a0.z = fmaf(h0.z, n0, a0.z); a0.w = fmaf(h0.w, n0, a0.w);
        a1.x = fmaf(h1.x, n1, a1.x); a1.y = fmaf(h1.y, n1, a1.y);
        a1.z = fmaf(h1.z, n1, a1.z); a1.w = fmaf(h1.w, n1, a1.w);
        a2.x = fmaf(h2.x, n2, a2.x); a2.y = fmaf(h2.y, n2, a2.y);
        a2.z = fmaf(h2.z, n2, a2.z); a2.w = fmaf(h2.w, n2, a2.w);
        a3.x = fmaf(h3.x, n3, a3.x); a3.y = fmaf(h3.y, n3, a3.y);
        a3.z = fmaf(h3.z, n3, a3.z); a3.w = fmaf(h3.w, n3, a3.w);
    }
    for (; j < end; j++) {
        int2 p0 = g_csr[j];
        float4 h0 = h4_load(hh, p0.x * 16 + g);
        float n0 = __int_as_float(p0.y);
        a0.x = fmaf(h0.x, n0, a0.x); a0.y = fmaf(h0.y, n0, a0.y);
        a0.z = fmaf(h0.z, n0, a0.z); a0.w = fmaf(h0.w, n0, a0.w);
    }
    a0.x += a1.x + a2.x + a3.x;
    a0.y += a1.y + a2.y + a3.y;
    a0.z += a1.z + a2.z + a3.z;
    a0.w += a1.w + a2.w + a3.w;
    *(float4*)(g_agg + node * DD + g * 4) = a0;
}

// ---------------- fused mean pool + projection (binary search, no atomics) ----------
__global__ void k_poolout(const int* __restrict__ bs, const float* __restrict__ Wout,
                          const float* __restrict__ bout, float* __restrict__ out) {
    __shared__ float sh[128];
    __shared__ float sp[DD];
    int gr = blockIdx.x;
    int t = threadIdx.x;  // 128 threads

    // lower_bound(bs, gr) and lower_bound(bs, gr+1): bs is sorted
    int lo = 0, hi = NN;
    while (lo < hi) { int m = (lo + hi) >> 1; if (bs[m] < gr) lo = m + 1; else hi = m; }
    int s = lo;
    hi = NN;
    while (lo < hi) { int m = (lo + hi) >> 1; if (bs[m] < gr + 1) lo = m + 1; else hi = m; }
    int e = lo;
    int cnt = e - s;

    int c = t & 63, half = t >> 6;
    float acc = 0.f;
    for (int r = s + half; r < e; r += 2)
        acc += g_agg[r * DD + c];
    sh[t] = acc;
    __syncthreads();
    if (t < DD) sp[t] = (sh[t] + sh[t + 64]) / fmaxf((float)cnt, 1.f);
    __syncthreads();
    if (t < NT) {
        float a = bout[t];
#pragma unroll
        for (int k = 0; k < DD; k++) a = fmaf(sp[k], Wout[k * NT + t], a);
        out[gr * NT + t] = a;
    }
}

// ---------------- host ----------------
extern "C" void kernel_launch(void* const* d_in, const int* in_sizes, int n_in,
                              void* d_out, int out_size) {
    const float* x    = (const float*)d_in[0];
    const float* W1   = (const float*)d_in[1];
    const float* b1   = (const float*)d_in[2];
    const float* W2   = (const float*)d_in[3];
    const float* b2   = (const float*)d_in[4];
    const float* W3   = (const float*)d_in[5];
    const float* b3   = (const float*)d_in[6];
    const float* Wout = (const float*)d_in[7];
    const float* bout = (const float*)d_in[8];
    const int* ei     = (const int*)d_in[9];    // int32 (JAX x64 disabled)
    const int* bs     = (const int*)d_in[10];   // int32
    float* out = (float*)d_out;

    const int* src = ei;        // edge_index[0]
    const int* dst = ei + NE;   // edge_index[1]

    unsigned int* p_hh;
    float* p_agg;
    cudaGetSymbolAddress((void**)&p_hh, g_hh);
    cudaGetSymbolAddress((void**)&p_agg, g_agg);

    const int TB = 256;
    const int gN   = (NN + TB - 1) / TB;
    const int gE   = (NE + TB - 1) / TB;
    const int gAgg = NN / 16;                     // 6250
    const int gGemm = (NN + 63) / 64;             // 1563

    // -- structure prep: degree -> offsets -> CSR by dst --
    k_zero<<<gN, TB>>>();
    k_deg<<<gE, TB>>>(dst);
    k_scan1<<<SCAN_G, SCAN_B>>>();
    k_scan3<<<SCAN_G, SCAN_B>>>();
    k_fill<<<gE, TB>>>(src, dst);

    // -- layer 1: agg = A_hat @ (x @ W1) + b1 --
    k_gemm<<<gGemm, TB>>>(x, W1, p_hh, 0);
    k_agg<<<gAgg, TB>>>(b1);

    // -- layer 2 (relu fused into gemm A-load) --
    k_gemm<<<gGemm, TB>>>(p_agg, W2, p_hh, 1);
    k_agg<<<gAgg, TB>>>(b2);

    // -- layer 3 --
    k_gemm<<<gGemm, TB>>>(p_agg, W3, p_hh, 1);
    k_agg<<<gAgg, TB>>>(b3);

    // -- fused mean pool + output projection --
    k_poolout<<<NG, 128>>>(bs, Wout, bout, out);
}

// round 10
// speedup vs baseline: 2.3624x; 1.1055x over previous
#include <cuda_runtime.h>
#include <cuda_fp16.h>
#include <math.h>

#define NN 100000
#define NE 1600000
#define DD 64
#define NG 512
#define NT 100

#define SCAN_B 1024
#define SCAN_G 98          // ceil(100000/1024)

// ---------------- device scratch (no allocations allowed) ----------------
__device__ __align__(16) unsigned int g_hh[NN * 32];  // h in half2: 64 halves = 128B/row
__device__ __align__(16) float g_agg[NN * DD];        // aggregation output (pre-relu, fp32)
__device__ int   g_degi[NN];
__device__ int   g_incl[NN];
__device__ int   g_bsum[SCAN_G];
__device__ int   g_off[NN + 1];    // CSR row offsets (by dst)
__device__ int   g_cur[NN];
__device__ float g_dinv[NN];
__device__ __align__(8) int2 g_csr[NE];  // .x = src node, .y = norm bits

// ---------------- zero degree ----------------
__global__ void k_zero() {
    int i = blockIdx.x * blockDim.x + threadIdx.x;
    if (i < NN) g_degi[i] = 0;
}

// ---------------- degree histogram ----------------
__global__ void k_deg(const int* __restrict__ dst) {
    int e = blockIdx.x * blockDim.x + threadIdx.x;
    if (e < NE) atomicAdd(&g_degi[dst[e]], 1);
}

// ---------------- prefix scan (2 kernels) ----------------
__global__ void k_scan1() {
    __shared__ int sh[SCAN_B];
    int i = blockIdx.x * SCAN_B + threadIdx.x;
    int v = (i < NN) ? g_degi[i] : 0;
    sh[threadIdx.x] = v;
    __syncthreads();
#pragma unroll
    for (int ofs = 1; ofs < SCAN_B; ofs <<= 1) {
        int t = (threadIdx.x >= ofs) ? sh[threadIdx.x - ofs] : 0;
        __syncthreads();
        sh[threadIdx.x] += t;
        __syncthreads();
    }
    if (i < NN) g_incl[i] = sh[threadIdx.x];
    if (threadIdx.x == SCAN_B - 1) g_bsum[blockIdx.x] = sh[SCAN_B - 1];
}

// merged: each block redundantly scans the 98 block sums, then applies.
__global__ void k_scan3() {
    __shared__ int sb[128];
    int t = threadIdx.x;
    if (t < 128) sb[t] = (t < SCAN_G) ? g_bsum[t] : 0;
    __syncthreads();
#pragma unroll
    for (int ofs = 1; ofs < 128; ofs <<= 1) {
        int v = (t < 128 && t >= ofs) ? sb[t - ofs] : 0;
        __syncthreads();
        if (t < 128) sb[t] += v;
        __syncthreads();
    }
    int bpre = (blockIdx.x == 0) ? 0 : sb[blockIdx.x - 1];
    int i = blockIdx.x * SCAN_B + t;
    if (i < NN) {
        int deg = g_degi[i];
        int off = g_incl[i] - deg + bpre;  // exclusive
        g_off[i] = off;
        g_cur[i] = off;
        g_dinv[i] = rsqrtf((float)deg + 1.f);
        if (i == NN - 1) g_off[NN] = NE;
    }
}

// ---------------- CSR fill ----------------
__global__ void k_fill(const int* __restrict__ src, const int* __restrict__ dst) {
    int e = blockIdx.x * blockDim.x + threadIdx.x;
    if (e < NE) {
        int s = src[e], d = dst[e];
        int slot = atomicAdd(&g_cur[d], 1);
        float n = g_dinv[s] * g_dinv[d];
        g_csr[slot] = make_int2(s, __float_as_int(n));
    }
}

// ---------------- GEMM via HMMA: Ch[n,64](fp16) = relu?(A[n,64]) @ W[64,64] ----
// 256 threads = 8 warps, 64 rows/block. Warp w: m-tile (w>>1)*16, n-tiles (w&1)*32..+31.
// mma.sync.m16n8k16.row.col.f32.f16.f16.f32; fragments loaded as contiguous half2.
#define SAP 72   // padded row stride in halves (conflict-free fragment loads)

__global__ void k_gemm(const float* __restrict__ A, const float* __restrict__ W,
                       unsigned int* __restrict__ Ch, int relu) {
    __shared__ __half sA[64 * SAP];
    __shared__ __half sWt[64 * SAP];   // sWt[n][k] = W[k][n]
    int tid = threadIdx.x;
    int rbase = blockIdx.x * 64;

    // load W (64x64 fp32, row-major [k][n]) transposed into fp16 sWt[n][k]
    {
        const float4* W4 = (const float4*)W;
#pragma unroll
        for (int i = 0; i < 4; i++) {
            int idx = tid + i * 256;          // 0..1023 float4s
            int k = idx >> 4;
            int n4 = (idx & 15) * 4;
            float4 w = W4[idx];
            sWt[(n4 + 0) * SAP + k] = __float2half(w.x);
            sWt[(n4 + 1) * SAP + k] = __float2half(w.y);
            sWt[(n4 + 2) * SAP + k] = __float2half(w.z);
            sWt[(n4 + 3) * SAP + k] = __float2half(w.w);
        }
    }
    // load A tile (64 rows fp32) -> fp16 smem, optional relu
    {
        const float4* A4 = (const float4*)A;
#pragma unroll
        for (int i = 0; i < 4; i++) {
            int idx = tid + i * 256;          // 0..1023 float4s
            int r = idx >> 4;                 // 0..63
            int c4 = (idx & 15) * 4;
            int gr = rbase + r;
            float4 v = make_float4(0.f, 0.f, 0.f, 0.f);
            if (gr < NN) v = A4[(long)gr * 16 + (idx & 15)];
            if (relu) {
                v.x = fmaxf(v.x, 0.f); v.y = fmaxf(v.y, 0.f);
                v.z = fmaxf(v.z, 0.f); v.w = fmaxf(v.w, 0.f);
            }
            __half2 lo = __floats2half2_rn(v.x, v.y);
            __half2 hi = __floats2half2_rn(v.z, v.w);
            *(__half2*)&sA[r * SAP + c4]     = lo;
            *(__half2*)&sA[r * SAP + c4 + 2] = hi;
        }
    }
    __syncthreads();

    int w = tid >> 5;
    int lane = tid & 31;
    int g = lane >> 2;       // group 0..7
    int t4 = lane & 3;       // thread-in-group 0..3
    int m0 = (w >> 1) * 16;
    int n0 = (w & 1) * 32;

    float c[4][4];           // 4 n-tiles x 4 f32 accum
#pragma unroll
    for (int i = 0; i < 4; i++)
#pragma unroll
        for (int j = 0; j < 4; j++) c[i][j] = 0.f;

#pragma unroll
    for (int kk = 0; kk < 4; kk++) {
        int k0 = kk * 16;
        unsigned int a0 = *(unsigned int*)&sA[(m0 + g) * SAP + k0 + 2 * t4];
        unsigned int a1 = *(unsigned int*)&sA[(m0 + g + 8) * SAP + k0 + 2 * t4];
        unsigned int a2 = *(unsigned int*)&sA[(m0 + g) * SAP + k0 + 2 * t4 + 8];
        unsigned int a3 = *(unsigned int*)&sA[(m0 + g + 8) * SAP + k0 + 2 * t4 + 8];
#pragma unroll
        for (int nt = 0; nt < 4; nt++) {
            int n = n0 + nt * 8;
            unsigned int b0 = *(unsigned int*)&sWt[(n + g) * SAP + k0 + 2 * t4];
            unsigned int b1 = *(unsigned int*)&sWt[(n + g) * SAP + k0 + 2 * t4 + 8];
            asm volatile(
                "mma.sync.aligned.m16n8k16.row.col.f32.f16.f16.f32 "
                "{%0,%1,%2,%3}, {%4,%5,%6,%7}, {%8,%9}, {%0,%1,%2,%3};\n"
                : "+f"(c[nt][0]), "+f"(c[nt][1]), "+f"(c[nt][2]), "+f"(c[nt][3])
                : "r"(a0), "r"(a1), "r"(a2), "r"(a3), "r"(b0), "r"(b1));
        }
    }

    // store: D(16x8) f32 -> half2 words. c0:(g,2t) c1:(g,2t+1) c2:(g+8,2t) c3:(g+8,2t+1)
#pragma unroll
    for (int nt = 0; nt < 4; nt++) {
        int wcol = ((n0 + nt * 8) >> 1) + t4;   // half2 word index within row
        int r0 = rbase + m0 + g;
        int r1 = r0 + 8;
        __half2 p0 = __floats2half2_rn(c[nt][0], c[nt][1]);
        __half2 p1 = __floats2half2_rn(c[nt][2], c[nt][3]);
        if (r0 < NN) Ch[(long)r0 * 32 + wcol] = *(unsigned int*)&p0;
        if (r1 < NN) Ch[(long)r1 * 32 + wcol] = *(unsigned int*)&p1;
    }
}

// ---------------- aggregation (gather fp16 rows, no atomics, MLP=4) ----------------
__device__ __forceinline__ float4 h4_load(const uint2* __restrict__ hh, int idx) {
    uint2 v = hh[idx];
    __half2 lo = *(__half2*)&v.x;
    __half2 hi = *(__half2*)&v.y;
    float2 f0 = __half22float2(lo);
    float2 f1 = __half22float2(hi);
    return make_float4(f0.x, f0.y, f1.x, f1.y);
}

__global__ void k_agg(const float* __restrict__ b) {
    const uint2* hh = (const uint2*)g_hh;   // 16 uint2 per row
    int tid = threadIdx.x;
    int node = blockIdx.x * 16 + (tid >> 4);
    int g = tid & 15;
    int start = g_off[node];
    int end   = g_off[node + 1];
    float di = g_dinv[node];
    float d2 = di * di;
    float4 hs = h4_load(hh, node * 16 + g);
    float4 bb = *(const float4*)(b + g * 4);
    float4 a0, a1, a2, a3;
    a0.x = fmaf(hs.x, d2, bb.x);
    a0.y = fmaf(hs.y, d2, bb.y);
    a0.z = fmaf(hs.z, d2, bb.z);
    a0.w = fmaf(hs.w, d2, bb.w);
    a1 = make_float4(0.f, 0.f, 0.f, 0.f);
    a2 = a1; a3 = a1;
    int j = start;
    for (; j + 4 <= end; j += 4) {
        int2 p0 = g_csr[j];
        int2 p1 = g_csr[j + 1];
        int2 p2 = g_csr[j + 2];
        int2 p3 = g_csr[j + 3];
        float4 h0 = h4_load(hh, p0.x * 16 + g);
        float4 h1 = h4_load(hh, p1.x * 16 + g);
        float4 h2 = h4_load(hh, p2.x * 16 + g);
        float4 h3 = h4_load(hh, p3.x * 16 + g);
        float n0 = __int_as_float(p0.y);
        float n1 = __int_as_float(p1.y);
        float n2 = __int_as_float(p2.y);
        float n3 = __int_as_float(p3.y);
        a0.x = fmaf(h0.x, n0, a0.x); a0.y = fmaf(h0.y, n0, a0.y);
        a0.z = fmaf(h0.z, n0, a0.z); a0.w = fmaf(h0.w, n0, a0.w);
        a1.x = fmaf(h1.x, n1, a1.x); a1.y = fmaf(h1.y, n1, a1.y);
        a1.z = fmaf(h1.z, n1, a1.z); a1.w = fmaf(h1.w, n1, a1.w);
        a2.x = fmaf(h2.x, n2, a2.x); a2.y = fmaf(h2.y, n2, a2.y);
        a2.z = fmaf(h2.z, n2, a2.z); a2.w = fmaf(h2.w, n2, a2.w);
        a3.x = fmaf(h3.x, n3, a3.x); a3.y = fmaf(h3.y, n3, a3.y);
        a3.z = fmaf(h3.z, n3, a3.z); a3.w = fmaf(h3.w, n3, a3.w);
    }
    for (; j < end; j++) {
        int2 p0 = g_csr[j];
        float4 h0 = h4_load(hh, p0.x * 16 + g);
        float n0 = __int_as_float(p0.y);
        a0.x = fmaf(h0.x, n0, a0.x); a0.y = fmaf(h0.y, n0, a0.y);
        a0.z = fmaf(h0.z, n0, a0.z); a0.w = fmaf(h0.w, n0, a0.w);
    }
    a0.x += a1.x + a2.x + a3.x;
    a0.y += a1.y + a2.y + a3.y;
    a0.z += a1.z + a2.z + a3.z;
    a0.w += a1.w + a2.w + a3.w;
    *(float4*)(g_agg + node * DD + g * 4) = a0;
}

// ---------------- fused mean pool + projection (binary search, no atomics) ----------
__global__ void k_poolout(const int* __restrict__ bs, const float* __restrict__ Wout,
                          const float* __restrict__ bout, float* __restrict__ out) {
    __shared__ float sh[128];
    __shared__ float sp[DD];
    int gr = blockIdx.x;
    int t = threadIdx.x;  // 128 threads

    // lower_bound(bs, gr) and lower_bound(bs, gr+1): bs is sorted
    int lo = 0, hi = NN;
    while (lo < hi) { int m = (lo + hi) >> 1; if (bs[m] < gr) lo = m + 1; else hi = m; }
    int s = lo;
    hi = NN;
    while (lo < hi) { int m = (lo + hi) >> 1; if (bs[m] < gr + 1) lo = m + 1; else hi = m; }
    int e = lo;
    int cnt = e - s;

    int c = t & 63, half = t >> 6;
    float acc = 0.f;
    for (int r = s + half; r < e; r += 2)
        acc += g_agg[r * DD + c];
    sh[t] = acc;
    __syncthreads();
    if (t < DD) sp[t] = (sh[t] + sh[t + 64]) / fmaxf((float)cnt, 1.f);
    __syncthreads();
    if (t < NT) {
        float a = bout[t];
#pragma unroll
        for (int k = 0; k < DD; k++) a = fmaf(sp[k], Wout[k * NT + t], a);
        out[gr * NT + t] = a;
    }
}

// ---------------- host ----------------
extern "C" void kernel_launch(void* const* d_in, const int* in_sizes, int n_in,
                              void* d_out, int out_size) {
    const float* x    = (const float*)d_in[0];
    const float* W1   = (const float*)d_in[1];
    const float* b1   = (const float*)d_in[2];
    const float* W2   = (const float*)d_in[3];
    const float* b2   = (const float*)d_in[4];
    const float* W3   = (const float*)d_in[5];
    const float* b3   = (const float*)d_in[6];
    const float* Wout = (const float*)d_in[7];
    const float* bout = (const float*)d_in[8];
    const int* ei     = (const int*)d_in[9];    // int32 (JAX x64 disabled)
    const int* bs     = (const int*)d_in[10];   // int32
    float* out = (float*)d_out;

    const int* src = ei;        // edge_index[0]
    const int* dst = ei + NE;   // edge_index[1]

    unsigned int* p_hh;
    float* p_agg;
    cudaGetSymbolAddress((void**)&p_hh, g_hh);
    cudaGetSymbolAddress((void**)&p_agg, g_agg);

    const int TB = 256;
    const int gN   = (NN + TB - 1) / TB;
    const int gE   = (NE + TB - 1) / TB;
    const int gAgg = NN / 16;                     // 6250
    const int gGemm = (NN + 63) / 64;             // 1563

    // -- structure prep: degree -> offsets -> CSR by dst --
    k_zero<<<gN, TB>>>();
    k_deg<<<gE, TB>>>(dst);
    k_scan1<<<SCAN_G, SCAN_B>>>();
    k_scan3<<<SCAN_G, SCAN_B>>>();
    k_fill<<<gE, TB>>>(src, dst);

    // -- layer 1: agg = A_hat @ (x @ W1) + b1 --
    k_gemm<<<gGemm, TB>>>(x, W1, p_hh, 0);
    k_agg<<<gAgg, TB>>>(b1);

    // -- layer 2 (relu fused into gemm A-load) --
    k_gemm<<<gGemm, TB>>>(p_agg, W2, p_hh, 1);
    k_agg<<<gAgg, TB>>>(b2);

    // -- layer 3 --
    k_gemm<<<gGemm, TB>>>(p_agg, W3, p_hh, 1);
    k_agg<<<gAgg, TB>>>(b3);

    // -- fused mean pool + output projection --
    k_poolout<<<NG, 128>>>(bs, Wout, bout, out);
}